// round 10
// baseline (speedup 1.0000x reference)
#include <cuda_runtime.h>
#include <stdint.h>

#define NB 2
#define NH 4
#define NN 8192
#define NK 32
#define NROWS 8
#define PERM_ELEMS (NB * NN * NH * NK * NK)   // 67,108,864
#define IDX_BASE   PERM_ELEMS

typedef unsigned long long u64;
typedef unsigned int u32;
typedef unsigned short u16;

// Scratch (device globals -> no allocation)
__device__ u64 g_keys[NROWS * NN];
__device__ int g_inv [NROWS * NN];

__device__ __forceinline__ u32 f2u(float f) {
    u32 b = __float_as_uint(f);
    return (b & 0x80000000u) ? ~b : (b | 0x80000000u);
}

// -------------------------------------------------------------------------
// Stable LSD radix argsort: one CTA per row, 1024 threads, 4 passes x 8 bits,
// fully in shared memory. Stability: warps own contiguous 256-elem spans,
// iterations sequential, intra-warp rank via match_any + popc(below) ->
// scatter preserves original order within equal digits; LSD over the f2u
// value bits therefore yields exactly stable-ascending argsort.
// smem: keyA/keyB (u32 x 8192 each), idxA/idxB (u16 x 8192 each),
//       whist (32 warps x 256 bins), scan temps.  ~130 KB.
// -------------------------------------------------------------------------
__global__ void __launch_bounds__(1024) sortRadix(const float* __restrict__ r) {
    extern __shared__ u32 sm[];
    u32* keyA  = sm;                       // 8192
    u32* keyB  = keyA + NN;                // 8192
    u16* idxA  = (u16*)(keyB + NN);        // 8192
    u16* idxB  = idxA + NN;                // 8192
    u32* whist = (u32*)(idxB + NN);        // 32*256 = 8192
    u32* dscan = whist + 32 * 256;         // 256
    u32* wpart = dscan + 256;              // 8

    const unsigned FULL = 0xFFFFFFFFu;
    int row  = blockIdx.x;
    int tid  = threadIdx.x, lane = tid & 31, warp = tid >> 5;
    int base = warp << 8;                  // warp's contiguous 256-elem span
    const float* rr = r + row * NN;

    // load: keyA = f2u(value), idxA = original index
    for (int i = tid; i < NN; i += 1024) {
        keyA[i] = f2u(rr[i]);
        idxA[i] = (u16)i;
    }
    __syncthreads();

    u32 *ks = keyA, *kd = keyB;
    u16 *is = idxA, *id = idxB;

#pragma unroll
    for (int pass = 0; pass < 4; pass++) {
        int shift = pass << 3;

        // ---- zero per-warp histograms ----
        for (int z = tid; z < 32 * 256; z += 1024) whist[z] = 0;
        __syncthreads();

        // ---- histogram (leader-only RMW, no atomics) ----
        u32 myk[8], myd[8];
#pragma unroll
        for (int it = 0; it < 8; it++) {
            int e = base + (it << 5) + lane;
            u32 k = ks[e];
            u32 d = (k >> shift) & 255u;
            myk[it] = k; myd[it] = d;
            u32 peers = __match_any_sync(FULL, d);
            if (lane == (__ffs(peers) - 1))
                whist[(warp << 8) + d] += __popc(peers);
            __syncwarp();
        }
        __syncthreads();

        // ---- digit totals + exclusive scan over 256 bins ----
        u32 v = 0, x = 0;
        if (tid < 256) {
            u32 t = 0;
#pragma unroll 8
            for (int w = 0; w < 32; w++) t += whist[(w << 8) + tid];
            v = t; x = t;
#pragma unroll
            for (int o = 1; o < 32; o <<= 1) {
                u32 y = __shfl_up_sync(FULL, x, o);
                if (lane >= o) x += y;
            }
            if (lane == 31) wpart[tid >> 5] = x;    // warp-inclusive total
        }
        __syncthreads();
        if (tid < 256) {
            u32 add = 0;
#pragma unroll
            for (int w = 0; w < 8; w++) if (w < (tid >> 5)) add += wpart[w];
            dscan[tid] = add + x - v;               // exclusive prefix
        }
        __syncthreads();

        // ---- convert whist to per-warp scatter bases ----
        if (tid < 256) {
            u32 run = dscan[tid];
#pragma unroll 8
            for (int w = 0; w < 32; w++) {
                u32 c = whist[(w << 8) + tid];
                whist[(w << 8) + tid] = run;
                run += c;
            }
        }
        __syncthreads();

        // ---- stable scatter ----
#pragma unroll
        for (int it = 0; it < 8; it++) {
            u32 d = myd[it];
            u16 ix = is[base + (it << 5) + lane];
            u32 peers = __match_any_sync(FULL, d);
            u32 rnk = __popc(peers & ((1u << lane) - 1u));
            u32 bofs = whist[(warp << 8) + d];
            kd[bofs + rnk] = myk[it];
            id[bofs + rnk] = ix;
            __syncwarp();
            if (lane == (__ffs(peers) - 1))
                whist[(warp << 8) + d] = bofs + __popc(peers);
            __syncwarp();
        }
        __syncthreads();

        // swap buffers
        u32* tk = ks; ks = kd; kd = tk;
        u16* ti = is; is = id; id = ti;
    }

    // after 4 passes results are back in keyA/idxA (== ks/is)
    u64* gk  = g_keys + row * NN;
    int* inv = g_inv  + row * NN;
    for (int i = tid; i < NN; i += 1024) {
        u32 k = ks[i]; u32 ix = is[i];
        gk[i] = ((u64)k << 32) | ix;
        inv[ix] = i;
    }
}

// -------------------------------------------------------------------------
// Windows + perm generation (R9-validated): one warp per window; block
// covers (b, p0..p0+1) x all 4 h -> contiguous 32KB output span per block.
// -------------------------------------------------------------------------
__global__ void __launch_bounds__(256) windowsW(float* __restrict__ out) {
    const unsigned FULL = 0xFFFFFFFFu;
    const float E_M8  = 3.3546262790251185e-4f;   // exp(-8)
    const float E_P56 = 2.0916595960130657e+24f;  // exp(56)
    int lane = threadIdx.x & 31;
    int wib  = threadIdx.x >> 5;                  // 0..7
    int b    = blockIdx.x >> 12;                  // 0..1
    int g    = blockIdx.x & 4095;                 // p-group
    int p    = (g << 1) | (wib >> 2);
    int h    = wib & 3;
    int row  = (b << 2) | h;
    int rb   = row * NN;

    int s   = g_inv[rb + p];
    int pos = (s + lane) & (NN - 1);
    u64 key = g_keys[rb + pos];
    int idx = (int)((u32)key & 8191u);
    u32 u   = (u32)(key >> 32);

    u32 prevu = __shfl_up_sync(FULL, u, 1);
    int eq = (lane > 0 && pos != 0 && u == prevu) ? 1 : 0;
    unsigned mask = __ballot_sync(FULL, eq);

    int t = lane;
    unsigned above = (t == 31) ? 0u : (mask >> (t + 1));
    int t1 = t + (__ffs(~above) - 1);                // tie-run end
    unsigned below = ~mask & (0xFFFFFFFFu >> (31 - t));
    int t0 = 31 - __clz(below);                      // tie-run start
    int m  = NN - s; if (m > 32) m = 32;             // wrap point
    int greater = (t < m) ? (m - 1 - t1) : (m + 31 - t1);
    int rank = greater + (t - t0);

    int pack = (idx << 6) | rank;                    // idx distinct -> stable
#pragma unroll
    for (int k2 = 2; k2 <= 32; k2 <<= 1) {
#pragma unroll
        for (int j = k2 >> 1; j > 0; j >>= 1) {
            int o = __shfl_xor_sync(FULL, pack, j);
            bool asc = ((lane & k2) == 0);
            bool low = ((lane & j) == 0);
            bool take = (asc == low) ? (o < pack) : (o > pack);
            if (take) pack = o;
        }
    }

    __stcs(out + (size_t)IDX_BASE + (size_t)(rb + p) * NK + lane,
           (float)(pack >> 6));
    int rk = pack & 63;

    float e = __expf(-2.0f * (float)lane);           // lane m holds exp(-2m)
    int c0 = (lane & 7) * 4;
    int arow = lane >> 3;

    int mm[4]; float v[4];
    {
        int r0 = __shfl_sync(FULL, rk, c0);
        int r1 = __shfl_sync(FULL, rk, c0 + 1);
        int r2 = __shfl_sync(FULL, rk, c0 + 2);
        int r3 = __shfl_sync(FULL, rk, c0 + 3);
        mm[0] = (arow - r0) & 31;  mm[1] = (arow - r1) & 31;
        mm[2] = (arow - r2) & 31;  mm[3] = (arow - r3) & 31;
        v[0] = __shfl_sync(FULL, e, mm[0]);
        v[1] = __shfl_sync(FULL, e, mm[1]);
        v[2] = __shfl_sync(FULL, e, mm[2]);
        v[3] = __shfl_sync(FULL, e, mm[3]);
    }

    float* po = out + ((size_t)((b * NN + p) * NH + h) << 10);  // (B,N,H,K,K)

    __stcs(reinterpret_cast<float4*>(po + arow * 32 + c0),
           make_float4(v[0], v[1], v[2], v[3]));
#pragma unroll
    for (int rnd = 1; rnd < 8; rnd++) {
#pragma unroll
        for (int c = 0; c < 4; c++) {
            mm[c] += 4;
            bool wrap = mm[c] >= 32;
            v[c] *= wrap ? E_P56 : E_M8;
            if (wrap) mm[c] -= 32;
        }
        int a = rnd * 4 + arow;
        __stcs(reinterpret_cast<float4*>(po + a * 32 + c0),
               make_float4(v[0], v[1], v[2], v[3]));
    }
}

extern "C" void kernel_launch(void* const* d_in, const int* in_sizes, int n_in,
                              void* d_out, int out_size) {
    const float* ranking = (const float*)d_in[0];   // (B,H,N,1) f32
    float* out = (float*)d_out;

    const int RADIX_SMEM = 2 * NN * 4 + 2 * NN * 2 + 32 * 256 * 4
                         + 256 * 4 + 8 * 4 + 256;   // ~132.5 KB
    cudaFuncSetAttribute(sortRadix, cudaFuncAttributeMaxDynamicSharedMemorySize,
                         RADIX_SMEM);

    sortRadix<<<NROWS, 1024, RADIX_SMEM>>>(ranking);
    windowsW<<<8192, 256>>>(out);
}

// round 11
// speedup vs baseline: 1.6792x; 1.6792x over previous
#include <cuda_runtime.h>
#include <stdint.h>

#define NB 2
#define NH 4
#define NN 8192
#define NK 32
#define NROWS 8
#define PERM_ELEMS (NB * NN * NH * NK * NK)   // 67,108,864
#define IDX_BASE   PERM_ELEMS

typedef unsigned long long u64;
typedef unsigned int u32;

// Scratch (device globals -> no allocation)
__device__ u64 g_keys[NROWS * NN];
__device__ int g_inv [NROWS * NN];

__device__ __forceinline__ u32 f2u(float f) {
    u32 b = __float_as_uint(f);
    return (b & 0x80000000u) ? ~b : (b | 0x80000000u);
}
__device__ __forceinline__ void cswap(u64& a, u64& b, bool asc) {
    if ((a > b) == asc) { u64 t = a; a = b; b = t; }
}
__device__ __forceinline__ void cluster_sync() {
    asm volatile("barrier.cluster.arrive.aligned;" ::: "memory");
    asm volatile("barrier.cluster.wait.aligned;" ::: "memory");
}
__device__ __forceinline__ u32 smem_u32(const void* p) {
    u32 a;
    asm("{ .reg .u64 t; cvta.to.shared.u64 t, %1; cvt.u32.u64 %0, t; }"
        : "=r"(a) : "l"(p));
    return a;
}
__device__ __forceinline__ u32 mapa_rank(u32 local, u32 rank) {
    u32 r;
    asm("mapa.shared::cluster.u32 %0, %1, %2;" : "=r"(r) : "r"(local), "r"(rank));
    return r;
}

// Generic warp-segment finisher for small k (asc varies inside segment).
// smem steps j=jhi..4, then j=2,1 in registers on consecutive quads.
__device__ __forceinline__ void warp_gen(u64* sh, int seg, int gseg,
                                         int lane, int jhi, int k) {
    for (int j = jhi; j >= 4; j >>= 1) {
#pragma unroll
        for (int t = lane; t < 64; t += 32) {
            int i = ((t & ~(j - 1)) << 1) | (t & (j - 1));
            int p = i | j;
            bool asc = (((gseg + i) & k) == 0);
            u64 a = sh[seg + i], b = sh[seg + p];
            if ((a > b) == asc) { sh[seg + i] = b; sh[seg + p] = a; }
        }
        __syncwarp();
    }
    int eb = seg + (lane << 2);
    bool asc = (((gseg + (lane << 2)) & k) == 0);
    u64 e0 = sh[eb], e1 = sh[eb + 1], e2 = sh[eb + 2], e3 = sh[eb + 3];
    cswap(e0, e2, asc); cswap(e1, e3, asc);    // j=2
    cswap(e0, e1, asc); cswap(e2, e3, asc);    // j=1
    sh[eb] = e0; sh[eb + 1] = e1; sh[eb + 2] = e2; sh[eb + 3] = e3;
    __syncwarp();
}

// Segment finisher for k>=256 (asc uniform per 128-elem segment):
// fused {j=64,32} in registers (stride-32), smem j=16,8,4, reg tail j=2,1.
__device__ __forceinline__ void warp_finish64(u64* sh, int seg, int lane,
                                              bool asc) {
    int b = seg + lane;
    {
        u64 e0 = sh[b], e1 = sh[b + 32], e2 = sh[b + 64], e3 = sh[b + 96];
        cswap(e0, e2, asc); cswap(e1, e3, asc);    // j=64
        cswap(e0, e1, asc); cswap(e2, e3, asc);    // j=32
        sh[b] = e0; sh[b + 32] = e1; sh[b + 64] = e2; sh[b + 96] = e3;
    }
    __syncwarp();
    for (int j = 16; j >= 4; j >>= 1) {
#pragma unroll
        for (int t = lane; t < 64; t += 32) {
            int i = ((t & ~(j - 1)) << 1) | (t & (j - 1));
            int p = i | j;
            u64 a = sh[seg + i], bb = sh[seg + p];
            if ((a > bb) == asc) { sh[seg + i] = bb; sh[seg + p] = a; }
        }
        __syncwarp();
    }
    int eb = seg + (lane << 2);
    u64 f0 = sh[eb], f1 = sh[eb + 1], f2 = sh[eb + 2], f3 = sh[eb + 3];
    cswap(f0, f2, asc); cswap(f1, f3, asc);    // j=2
    cswap(f0, f1, asc); cswap(f2, f3, asc);    // j=1
    sh[eb] = f0; sh[eb + 1] = f1; sh[eb + 2] = f2; sh[eb + 3] = f3;
    __syncwarp();
}

// Fused {j=1024, j=512} in registers: stride-512 ownership. asc uniform.
__device__ __forceinline__ void fuse_1024_512(u64* sh, int tid, bool asc) {
    u64 e0 = sh[tid], e1 = sh[tid + 512], e2 = sh[tid + 1024], e3 = sh[tid + 1536];
    cswap(e0, e2, asc); cswap(e1, e3, asc);    // j=1024
    cswap(e0, e1, asc); cswap(e2, e3, asc);    // j=512
    sh[tid] = e0; sh[tid + 512] = e1; sh[tid + 1024] = e2; sh[tid + 1536] = e3;
    __syncthreads();
}

// Fused {j=256, j=128} in registers: stride-128 ownership. asc per-thread.
__device__ __forceinline__ void fuse_256_128(u64* sh, int tid, bool asc) {
    int b = ((tid >> 7) << 9) | (tid & 127);
    u64 e0 = sh[b], e1 = sh[b + 128], e2 = sh[b + 256], e3 = sh[b + 384];
    cswap(e0, e2, asc); cswap(e1, e3, asc);    // j=256
    cswap(e0, e1, asc); cswap(e2, e3, asc);    // j=128
    sh[b] = e0; sh[b + 128] = e1; sh[b + 256] = e2; sh[b + 384] = e3;
    __syncthreads();
}

// Block-wide step over the 2048-elem chunk.
__device__ __forceinline__ void block_step(u64* sh, int gbase, int tid,
                                           int j, int k) {
#pragma unroll
    for (int t = tid; t < 1024; t += 512) {
        int i = ((t & ~(j - 1)) << 1) | (t & (j - 1));
        int p = i | j;
        bool asc = (((gbase + i) & k) == 0);
        u64 a = sh[i], b = sh[p];
        if ((a > b) == asc) { sh[i] = b; sh[p] = a; }
    }
    __syncthreads();
}

// Cross-CTA exchange via DSMEM (keys unique -> both sides decide consistently).
__device__ __forceinline__ void exchange(u64* sh, u32 shbase, int partner,
                                         bool keep_min, int tid) {
    cluster_sync();                         // peers' data finalized
    u64 peer[4];
    u32 remote = mapa_rank(shbase, (u32)partner);
#pragma unroll
    for (int m = 0; m < 4; m++) {
        u32 addr = remote + (u32)((tid + (m << 9)) << 3);
        asm volatile("ld.shared::cluster.b64 %0, [%1];" : "=l"(peer[m]) : "r"(addr));
    }
    cluster_sync();                         // all reads done before overwrite
#pragma unroll
    for (int m = 0; m < 4; m++) {
        int l = tid + (m << 9);
        u64 mine = sh[l];
        bool take = keep_min ? (peer[m] < mine) : (peer[m] > mine);
        if (take) sh[l] = peer[m];
    }
    // NOTE: next phase (fuse_1024_512) reads the SAME slots this thread wrote
    // -> thread-local ordering, no barrier needed here.
}

// -------------------------------------------------------------------------
// Full stable argsort of 8 rows x 8192, ONE launch.
// 8 clusters x 4 CTAs, 2048-elem chunk per CTA, end-to-end in smem.
// Register-fused phases replace over half the block-wide smem steps.
// -------------------------------------------------------------------------
__global__ void __launch_bounds__(512) __cluster_dims__(4, 1, 1)
sortCluster(const float* __restrict__ r) {
    __shared__ u64 sh[2048];
    int tid  = threadIdx.x, lane = tid & 31, warp = tid >> 5;
    int row  = blockIdx.x >> 2;
    int rank = blockIdx.x & 3;
    int base = rank << 11;
    const float* rr = r + row * NN;
    u32 shbase = smem_u32(sh);
    int seg  = warp << 7;                   // warp-private 128-elem segment
    int gseg = base + seg;

    // load float4, k=2 and k=4 in registers, store quads (warp-local coherence)
    {
        int q = tid << 2;
        float4 f = *reinterpret_cast<const float4*>(rr + base + q);
        u64 e0 = ((u64)f2u(f.x) << 32) | (u32)(base + q);
        u64 e1 = ((u64)f2u(f.y) << 32) | (u32)(base + q + 1);
        u64 e2 = ((u64)f2u(f.z) << 32) | (u32)(base + q + 2);
        u64 e3 = ((u64)f2u(f.w) << 32) | (u32)(base + q + 3);
        cswap(e0, e1, true); cswap(e2, e3, false);            // k=2
        bool a4 = ((tid & 1) == 0);                           // k=4
        cswap(e0, e2, a4); cswap(e1, e3, a4);
        cswap(e0, e1, a4); cswap(e2, e3, a4);
        sh[q] = e0; sh[q + 1] = e1; sh[q + 2] = e2; sh[q + 3] = e3;
        __syncwarp();
    }

    // k = 8..128: warp-local generic (asc varies inside segment)
    for (int k = 8; k <= 128; k <<= 1)
        warp_gen(sh, seg, gseg, lane, k >> 1, k);
    __syncthreads();

    // ---- k=256 ----
    block_step(sh, base, tid, 128, 256);
    warp_finish64(sh, seg, lane, ((gseg & 256) == 0));
    __syncthreads();
    // ---- k=512 ----
    fuse_256_128(sh, tid, ((tid >> 7) & 1) == 0);
    warp_finish64(sh, seg, lane, ((gseg & 512) == 0));
    __syncthreads();
    // ---- k=1024 ----
    block_step(sh, base, tid, 512, 1024);
    fuse_256_128(sh, tid, (tid >> 7) < 2);
    warp_finish64(sh, seg, lane, ((gseg & 1024) == 0));
    __syncthreads();
    // ---- k=2048 ----
    {
        bool A = ((base & 2048) == 0);
        fuse_1024_512(sh, tid, A);
        fuse_256_128(sh, tid, A);
        warp_finish64(sh, seg, lane, A);
    }
    // ---- k=4096: cross-CTA j=2048, then local (cluster_sync = barrier) ----
    exchange(sh, shbase, rank ^ 1, ((rank ^ (rank >> 1)) & 1) == 0, tid);
    {
        bool A = ((base & 4096) == 0);
        fuse_1024_512(sh, tid, A);
        fuse_256_128(sh, tid, A);
        warp_finish64(sh, seg, lane, A);
    }
    // ---- k=8192 (asc): cross j=4096, j=2048, then local ----
    exchange(sh, shbase, rank ^ 2, rank < 2, tid);
    exchange(sh, shbase, rank ^ 1, (rank & 1) == 0, tid);
    fuse_1024_512(sh, tid, true);
    fuse_256_128(sh, tid, true);
    warp_finish64(sh, seg, lane, true);

    // ---- extract (quad-local: slots this thread just wrote) ----
    u64* gk  = g_keys + row * NN + base;
    int* inv = g_inv  + row * NN;
    int eb = tid << 2;
#pragma unroll
    for (int m = 0; m < 4; m++) {
        u64 key = sh[eb + m];
        gk[eb + m] = key;
        inv[(u32)key & 8191u] = base + eb + m;
    }
}

// -------------------------------------------------------------------------
// Windows + perm generation (R9-validated, 41.5us): one warp per window;
// block covers (b, p0..p0+1) x all 4 h -> contiguous 32KB output span.
// -------------------------------------------------------------------------
__global__ void __launch_bounds__(256) windowsW(float* __restrict__ out) {
    const unsigned FULL = 0xFFFFFFFFu;
    const float E_M8  = 3.3546262790251185e-4f;   // exp(-8)
    const float E_P56 = 2.0916595960130657e+24f;  // exp(56)
    int lane = threadIdx.x & 31;
    int wib  = threadIdx.x >> 5;                  // 0..7
    int b    = blockIdx.x >> 12;                  // 0..1
    int g    = blockIdx.x & 4095;                 // p-group
    int p    = (g << 1) | (wib >> 2);
    int h    = wib & 3;
    int row  = (b << 2) | h;
    int rb   = row * NN;

    int s   = g_inv[rb + p];
    int pos = (s + lane) & (NN - 1);
    u64 key = g_keys[rb + pos];
    int idx = (int)((u32)key & 8191u);
    u32 u   = (u32)(key >> 32);

    u32 prevu = __shfl_up_sync(FULL, u, 1);
    int eq = (lane > 0 && pos != 0 && u == prevu) ? 1 : 0;
    unsigned mask = __ballot_sync(FULL, eq);

    int t = lane;
    unsigned above = (t == 31) ? 0u : (mask >> (t + 1));
    int t1 = t + (__ffs(~above) - 1);                // tie-run end
    unsigned below = ~mask & (0xFFFFFFFFu >> (31 - t));
    int t0 = 31 - __clz(below);                      // tie-run start
    int m  = NN - s; if (m > 32) m = 32;             // wrap point
    int greater = (t < m) ? (m - 1 - t1) : (m + 31 - t1);
    int rank = greater + (t - t0);

    int pack = (idx << 6) | rank;                    // idx distinct -> stable
#pragma unroll
    for (int k2 = 2; k2 <= 32; k2 <<= 1) {
#pragma unroll
        for (int j = k2 >> 1; j > 0; j >>= 1) {
            int o = __shfl_xor_sync(FULL, pack, j);
            bool asc = ((lane & k2) == 0);
            bool low = ((lane & j) == 0);
            bool take = (asc == low) ? (o < pack) : (o > pack);
            if (take) pack = o;
        }
    }

    __stcs(out + (size_t)IDX_BASE + (size_t)(rb + p) * NK + lane,
           (float)(pack >> 6));
    int rk = pack & 63;

    float e = __expf(-2.0f * (float)lane);           // lane m holds exp(-2m)
    int c0 = (lane & 7) * 4;
    int arow = lane >> 3;

    int mm[4]; float v[4];
    {
        int r0 = __shfl_sync(FULL, rk, c0);
        int r1 = __shfl_sync(FULL, rk, c0 + 1);
        int r2 = __shfl_sync(FULL, rk, c0 + 2);
        int r3 = __shfl_sync(FULL, rk, c0 + 3);
        mm[0] = (arow - r0) & 31;  mm[1] = (arow - r1) & 31;
        mm[2] = (arow - r2) & 31;  mm[3] = (arow - r3) & 31;
        v[0] = __shfl_sync(FULL, e, mm[0]);
        v[1] = __shfl_sync(FULL, e, mm[1]);
        v[2] = __shfl_sync(FULL, e, mm[2]);
        v[3] = __shfl_sync(FULL, e, mm[3]);
    }

    float* po = out + ((size_t)((b * NN + p) * NH + h) << 10);  // (B,N,H,K,K)

    __stcs(reinterpret_cast<float4*>(po + arow * 32 + c0),
           make_float4(v[0], v[1], v[2], v[3]));
#pragma unroll
    for (int rnd = 1; rnd < 8; rnd++) {
#pragma unroll
        for (int c = 0; c < 4; c++) {
            mm[c] += 4;
            bool wrap = mm[c] >= 32;
            v[c] *= wrap ? E_P56 : E_M8;
            if (wrap) mm[c] -= 32;
        }
        int a = rnd * 4 + arow;
        __stcs(reinterpret_cast<float4*>(po + a * 32 + c0),
               make_float4(v[0], v[1], v[2], v[3]));
    }
}

extern "C" void kernel_launch(void* const* d_in, const int* in_sizes, int n_in,
                              void* d_out, int out_size) {
    const float* ranking = (const float*)d_in[0];   // (B,H,N,1) f32
    float* out = (float*)d_out;

    sortCluster<<<32, 512>>>(ranking);
    windowsW<<<8192, 256>>>(out);
}